// round 10
// baseline (speedup 1.0000x reference)
#include <cuda_runtime.h>
#include <cuda_bf16.h>
#include <float.h>
#include <math.h>

#define LANE_WEIGHT 1.0f
#define INV_TEMP    10.0f   // 1 / 0.1

// scratch (allocation-free rule: __device__ globals)
__device__ float g_ce_lane[65536];      // ce_per_lane, NL <= 65536
__device__ float g_sample_loss[8192];   // per-sample loss, B <= 8192
__device__ int   g_done = 0;            // last-block ticket (self-resetting)

__device__ __forceinline__ float fsqrt_approx(float x) {
    float r;
    asm("sqrt.approx.f32 %0, %1;" : "=f"(r) : "f"(x));
    return r;
}

__device__ __forceinline__
int find_sample(const int* __restrict__ cls_se, int B, int lane)
{
    int lo = 0, hi = B - 1;
    while (lo < hi) {
        int mid = (lo + hi + 1) >> 1;
        if (cls_se[2 * mid] <= lane) lo = mid; else hi = mid - 1;
    }
    return lo;
}

// ---------------------------------------------------------------------------
// Per-lane fused softmax CE (two entries per thread, warp-wide shuffles).
//   ce = tmax + log(sum exp(ts-tmax)) - (sum p*ts)/(sum p),
//   p = exp((score-smax)*INV_TEMP).
// ---------------------------------------------------------------------------
__device__ __forceinline__
float warp_lane_ce(bool actA, bool actB, float sA, float sB, float tA, float tB)
{
    float smax = fmaxf(sA, sB);
    float tmax = fmaxf(tA, tB);
    #pragma unroll
    for (int o = 16; o; o >>= 1) {
        smax = fmaxf(smax, __shfl_xor_sync(0xffffffffu, smax, o));
        tmax = fmaxf(tmax, __shfl_xor_sync(0xffffffffu, tmax, o));
    }
    float pA = actA ? expf((sA - smax) * INV_TEMP) : 0.0f;
    float pB = actB ? expf((sB - smax) * INV_TEMP) : 0.0f;
    float eA = actA ? expf(tA - tmax) : 0.0f;
    float eB = actB ? expf(tB - tmax) : 0.0f;
    float P  = pA + pB;
    float E  = eA + eB;
    float PT = (actA ? pA * tA : 0.0f) + (actB ? pB * tB : 0.0f);
    #pragma unroll
    for (int o = 16; o; o >>= 1) {
        P  += __shfl_xor_sync(0xffffffffu, P,  o);
        E  += __shfl_xor_sync(0xffffffffu, E,  o);
        PT += __shfl_xor_sync(0xffffffffu, PT, o);
    }
    return tmax + logf(E) - PT / P;
}

// ---------------------------------------------------------------------------
// Kernel A' (T == 50): streaming ADE + in-block lane CE.
//   - quad-per-trajectory streaming, no sync during the stream
//   - s_ts staged at entry (overlaps the candidate stream)
//   - ONE __syncthreads, then warp 0 does the fused CE in registers
// ---------------------------------------------------------------------------
__global__ __launch_bounds__(256)
void traj_lane_ce_T50_kernel(const float* __restrict__ traj_scores, // [NT]
                             const float* __restrict__ cand,        // [NT,50,2]
                             const float* __restrict__ gt,          // [B,50,2]
                             const float* __restrict__ scales,      // [B]
                             const int*   __restrict__ cls_se,      // [B,2]
                             const int*   __restrict__ trj_se,      // [NL,2]
                             int B)
{
    const int lane = blockIdx.x;
    const int tid  = threadIdx.x;

    const int ts_start = trj_se[2 * lane];
    const int ts_end   = trj_se[2 * lane + 1];
    int cnt = ts_end - ts_start;
    if (cnt > 64) cnt = 64;

    __shared__ float s_score[64];
    __shared__ float s_ts[64];

    // stage traj_scores early (independent load, overlaps candidate stream)
    if (tid < 64 && tid < cnt)
        s_ts[tid] = traj_scores[ts_start + tid];

    const int sample = find_sample(cls_se, B, lane);
    const float inv_scale = 1.0f / scales[sample];

    const int tl  = tid >> 2;          // trajectory within lane (0..63)
    const int sub = tid & 3;

    float acc0 = 0.0f, acc1 = 0.0f;
    if (tl < cnt) {
        const float4* base = reinterpret_cast<const float4*>(cand)
                             + (size_t)(ts_start + tl) * 25;
        const float2* gt2 = reinterpret_cast<const float2*>(gt) + sample * 50;
        #pragma unroll
        for (int j = 0; j < 7; j++) {
            const int r = sub + 4 * j;
            if (r < 25) {
                float4 v  = base[r];
                float2 g0 = __ldg(&gt2[2 * r]);
                float2 g1 = __ldg(&gt2[2 * r + 1]);
                float dx0 = v.x - g0.x, dy0 = v.y - g0.y;
                float dx1 = v.z - g1.x, dy1 = v.w - g1.y;
                acc0 += fsqrt_approx(fmaf(dx0, dx0, fmaf(dy0, dy0, 1e-12f)));
                acc1 += fsqrt_approx(fmaf(dx1, dx1, fmaf(dy1, dy1, 1e-12f)));
            }
        }
    }
    float acc = acc0 + acc1;
    acc += __shfl_xor_sync(0xffffffffu, acc, 1);
    acc += __shfl_xor_sync(0xffffffffu, acc, 2);

    if (sub == 0 && tl < cnt)
        s_score[tl] = -(acc * 0.02f) * inv_scale;
    __syncthreads();

    // warp 0: fused softmax CE over the lane's cnt trajectories
    if (tid >= 32) return;
    const bool actA = (tid < cnt);
    const bool actB = (tid + 32 < cnt);
    float sA = actA ? s_score[tid]      : -FLT_MAX;
    float sB = actB ? s_score[tid + 32] : -FLT_MAX;
    float tA = actA ? s_ts[tid]         : -FLT_MAX;
    float tB = actB ? s_ts[tid + 32]    : -FLT_MAX;
    float ce = warp_lane_ce(actA, actB, sA, sB, tA, tB);
    if (tid == 0) g_ce_lane[lane] = ce;
}

// ---------------------------------------------------------------------------
// Kernel 2 (fused tail): warp per sample + last-block deterministic mean.
// ---------------------------------------------------------------------------
__global__ __launch_bounds__(32)
void sample_final_kernel(const float* __restrict__ lane_scores,  // [NL]
                         const int*   __restrict__ oracle,       // [NL]
                         const int*   __restrict__ cls_se,       // [B, 2]
                         float* __restrict__ out, int B)
{
    const int b = blockIdx.x;
    const int i = threadIdx.x;
    const int s = cls_se[2 * b];
    const int e = cls_se[2 * b + 1];
    int cnt = e - s;
    if (cnt > 32) cnt = 32;

    const bool act = (i < cnt);
    float ls  = act ? lane_scores[s + i] : -FLT_MAX;
    bool  orc = act && (oracle[s + i] != 0);
    float ce  = orc ? g_ce_lane[s + i] : 0.0f;

    float m = ls;
    #pragma unroll
    for (int o = 16; o; o >>= 1) m = fmaxf(m, __shfl_xor_sync(0xffffffffu, m, o));

    float ev = act ? expf(ls - m) : 0.0f;
    float oc = orc ? 1.0f : 0.0f;
    float Z = ev, OC = oc, CE = ce;
    #pragma unroll
    for (int o = 16; o; o >>= 1) {
        Z  += __shfl_xor_sync(0xffffffffu, Z, o);
        OC += __shfl_xor_sync(0xffffffffu, OC, o);
        CE += __shfl_xor_sync(0xffffffffu, CE, o);
    }
    const float lse = logf(Z);
    float llc = orc ? (m + lse - ls) : 0.0f;
    float LL = llc;
    #pragma unroll
    for (int o = 16; o; o >>= 1) LL += __shfl_xor_sync(0xffffffffu, LL, o);

    if (i == 0)
        g_sample_loss[b] = (LL / OC) * LANE_WEIGHT + CE / OC;

    // ---- last-block-done: deterministic final mean over B samples ----
    __threadfence();
    __shared__ bool s_last;
    if (i == 0) {
        int t = atomicAdd(&g_done, 1);
        s_last = (t == gridDim.x - 1);
    }
    __syncthreads();
    if (!s_last) return;

    __threadfence();   // make all g_sample_loss writes visible
    float v = 0.0f;
    for (int k = i; k < B; k += 32) v += g_sample_loss[k];
    #pragma unroll
    for (int o = 16; o; o >>= 1) v += __shfl_xor_sync(0xffffffffu, v, o);
    if (i == 0) {
        out[0] = v / (float)B;
        *((volatile int*)&g_done) = 0;   // reset for next graph replay
    }
}

// ---------------------------------------------------------------------------
// Generic fallback (any T): block-per-lane ADE + in-block epilogue.
// ---------------------------------------------------------------------------
__global__ __launch_bounds__(256)
void traj_ce_kernel(const float* __restrict__ traj_scores,
                    const float* __restrict__ cand,
                    const float* __restrict__ gt,
                    const float* __restrict__ scales,
                    const int*   __restrict__ cls_se,
                    const int*   __restrict__ trj_se,
                    int B, int T)
{
    const int lane = blockIdx.x;
    const int tid  = threadIdx.x;

    const int ts_start = trj_se[2 * lane];
    const int ts_end   = trj_se[2 * lane + 1];
    int cnt = ts_end - ts_start;
    if (cnt > 64) cnt = 64;

    const int sample = find_sample(cls_se, B, lane);

    __shared__ __align__(8) float s_gt[1024];
    __shared__ float s_score[64], s_ts[64];

    const int t2 = T * 2;
    for (int i = tid; i < t2 && i < 1024; i += blockDim.x)
        s_gt[i] = gt[(size_t)sample * t2 + i];
    __syncthreads();

    const float inv_scale = 1.0f / scales[sample];

    const int q   = tid >> 2;
    const int sub = tid & 3;
    float acc = 0.0f;
    if (q < cnt) {
        const float2* base = reinterpret_cast<const float2*>(cand)
                             + (size_t)(ts_start + q) * T;
        const float2* g2 = reinterpret_cast<const float2*>(s_gt);
        #pragma unroll 4
        for (int t = sub; t < T; t += 4) {
            float2 c = base[t];
            float2 g = g2[t];
            float dx = c.x - g.x;
            float dy = c.y - g.y;
            acc += fsqrt_approx(fmaf(dx, dx, fmaf(dy, dy, 1e-12f)));
        }
    }
    acc += __shfl_xor_sync(0xffffffffu, acc, 1);
    acc += __shfl_xor_sync(0xffffffffu, acc, 2);

    if (sub == 0 && q < cnt) {
        float ade = acc / (float)T;
        s_score[q] = -ade * inv_scale;
        s_ts[q]    = traj_scores[ts_start + q];
    }
    __syncthreads();

    if (tid >= 32) return;
    const bool actA = (tid < cnt);
    const bool actB = (tid + 32 < cnt);
    float sA = actA ? s_score[tid]      : -FLT_MAX;
    float sB = actB ? s_score[tid + 32] : -FLT_MAX;
    float tA = actA ? s_ts[tid]         : -FLT_MAX;
    float tB = actB ? s_ts[tid + 32]    : -FLT_MAX;
    float ce = warp_lane_ce(actA, actB, sA, sB, tA, tB);
    if (tid == 0) g_ce_lane[lane] = ce;
}

__global__ __launch_bounds__(32)
void sample_loss_kernel(const float* __restrict__ lane_scores,
                        const int*   __restrict__ oracle,
                        const int*   __restrict__ cls_se)
{
    const int b = blockIdx.x;
    const int i = threadIdx.x;
    const int s = cls_se[2 * b];
    const int e = cls_se[2 * b + 1];
    int cnt = e - s;
    if (cnt > 32) cnt = 32;

    const bool act = (i < cnt);
    float ls  = act ? lane_scores[s + i] : -FLT_MAX;
    bool  orc = act && (oracle[s + i] != 0);
    float ce  = orc ? g_ce_lane[s + i] : 0.0f;

    float m = ls;
    #pragma unroll
    for (int o = 16; o; o >>= 1) m = fmaxf(m, __shfl_xor_sync(0xffffffffu, m, o));

    float ev = act ? expf(ls - m) : 0.0f;
    float oc = orc ? 1.0f : 0.0f;
    float Z = ev, OC = oc, CE = ce;
    #pragma unroll
    for (int o = 16; o; o >>= 1) {
        Z  += __shfl_xor_sync(0xffffffffu, Z, o);
        OC += __shfl_xor_sync(0xffffffffu, OC, o);
        CE += __shfl_xor_sync(0xffffffffu, CE, o);
    }
    const float lse = logf(Z);
    float llc = orc ? (m + lse - ls) : 0.0f;
    float LL = llc;
    #pragma unroll
    for (int o = 16; o; o >>= 1) LL += __shfl_xor_sync(0xffffffffu, LL, o);

    if (i == 0)
        g_sample_loss[b] = (LL / OC) * LANE_WEIGHT + CE / OC;
}

__global__ __launch_bounds__(256)
void final_mean_kernel(float* __restrict__ out, int B)
{
    __shared__ float red[256];
    const int tid = threadIdx.x;
    float v = 0.0f;
    for (int i = tid; i < B; i += 256) v += g_sample_loss[i];
    red[tid] = v;
    __syncthreads();
    for (int o = 128; o >= 32; o >>= 1) {
        if (tid < o) red[tid] += red[tid + o];
        __syncthreads();
    }
    if (tid < 32) {
        float a = red[tid];
        #pragma unroll
        for (int o = 16; o; o >>= 1) a += __shfl_xor_sync(0xffffffffu, a, o);
        if (tid == 0) out[0] = a / (float)B;
    }
}

// ---------------------------------------------------------------------------
extern "C" void kernel_launch(void* const* d_in, const int* in_sizes, int n_in,
                              void* d_out, int out_size)
{
    const float* lane_scores = (const float*)d_in[0];   // [NL]
    const float* traj_scores = (const float*)d_in[1];   // [NT, 1]
    const float* cand        = (const float*)d_in[2];   // [NT, T, 2]
    const float* gt          = (const float*)d_in[3];   // [B, T, 2]
    const float* scales      = (const float*)d_in[4];   // [B]
    const int*   oracle      = (const int*)  d_in[5];   // [NL]
    const int*   cls_se      = (const int*)  d_in[6];   // [B, 2]
    const int*   trj_se      = (const int*)  d_in[7];   // [NL, 2]

    const int NL = in_sizes[0];
    const int B  = in_sizes[6] / 2;
    const int T  = in_sizes[3] / (2 * B);

    if (T == 50 && NL <= 65536 && B <= 8192) {
        traj_lane_ce_T50_kernel<<<NL, 256>>>(traj_scores, cand, gt, scales,
                                             cls_se, trj_se, B);
        sample_final_kernel<<<B, 32>>>(lane_scores, oracle, cls_se,
                                       (float*)d_out, B);
    } else {
        traj_ce_kernel<<<NL, 256>>>(traj_scores, cand, gt, scales,
                                    cls_se, trj_se, B, T);
        sample_loss_kernel<<<B, 32>>>(lane_scores, oracle, cls_se);
        final_mean_kernel<<<1, 256>>>((float*)d_out, B);
    }
}